// round 3
// baseline (speedup 1.0000x reference)
#include <cuda_runtime.h>

#define B_      16
#define L_      65536
#define H_      64
#define K_      64
#define WARMUP  63
#define LOUT    (L_ - WARMUP)     /* 65473 */
#define TILE_T  256
#define TPB     256
#define XS_LEN  (TILE_T + 72)     /* covers t0l + h + 8 max = 319 */

typedef unsigned long long u64;

__device__ __forceinline__ u64 pack2(float lo, float hi) {
    u64 r; asm("mov.b64 %0, {%1, %2};" : "=l"(r) : "f"(lo), "f"(hi)); return r;
}
__device__ __forceinline__ void unpack2(u64 v, float& lo, float& hi) {
    asm("mov.b64 {%0, %1}, %2;" : "=f"(lo), "=f"(hi) : "l"(v));
}
// d = a*b + d  (packed 2x fp32, Blackwell FFMA2)
__device__ __forceinline__ void ffma2(u64& d, u64 a, u64 b) {
    asm("fma.rn.f32x2 %0, %1, %2, %3;" : "=l"(d) : "l"(a), "l"(b), "l"(d));
}

__global__ __launch_bounds__(TPB, 2)
void hankel_fb_kernel(const float* __restrict__ x,
                      const float* __restrict__ W,
                      const float* __restrict__ bias,
                      float* __restrict__ out)
{
    __shared__ float xs[XS_LEN];
    __shared__ float Wt[H_][K_];   // Wt[h][k] (transposed: broadcast float4 loads per warp)
    __shared__ float Sk[K_];       // per-filter weight sums

    const int tile   = blockIdx.x;
    const int b      = blockIdx.y;
    const int tid    = threadIdx.x;
    const int t_base = tile * TILE_T;

    const float* __restrict__ xb = x + (size_t)b * L_;
    for (int i = tid; i < XS_LEN; i += TPB) {
        int g = t_base + i;
        xs[i] = (g < L_) ? xb[g] : 0.0f;
    }
    for (int i = tid; i < K_ * H_; i += TPB) {
        int k = i >> 6, h = i & 63;
        Wt[h][k] = W[i];
    }
    __syncthreads();

    if (tid < K_) {
        float s = 0.0f;
        #pragma unroll
        for (int h = 0; h < H_; ++h) s += Wt[h][tid];
        Sk[tid] = s;
    }
    __syncthreads();

    const int lane = tid & 31;
    const int warp = tid >> 5;
    const int k0   = warp * 8;     // warp owns 8 filters (4 packed pairs)
    const int t0l  = lane * 8;     // lane owns 8 consecutive positions

    // packed accumulators: acc2[i][j] = {out[t0l+i][k0+2j], out[t0l+i][k0+2j+1]}
    u64 acc2[8][4];
    #pragma unroll
    for (int i = 0; i < 8; ++i)
        #pragma unroll
        for (int j = 0; j < 4; ++j) acc2[i][j] = 0ULL;

    // rolling x window, duplicated into both halves: slot (h+i)&7 holds {x,x}[t0l+h+i]
    u64 xd[8];
    #pragma unroll
    for (int i = 0; i < 8; ++i) { float v = xs[t0l + i]; xd[i] = pack2(v, v); }

    // ---- main loop: 64 h-steps x 32 FFMA2 each (ring indices compile-time via unroll-8) ----
    #pragma unroll 1
    for (int hb = 0; hb < 8; ++hb) {
        #pragma unroll
        for (int u = 0; u < 8; ++u) {
            const int h = hb * 8 + u;
            float4 w0 = *(const float4*)&Wt[h][k0];       // warp-broadcast, conflict-free
            float4 w1 = *(const float4*)&Wt[h][k0 + 4];
            u64 wp[4];
            wp[0] = pack2(w0.x, w0.y);
            wp[1] = pack2(w0.z, w0.w);
            wp[2] = pack2(w1.x, w1.y);
            wp[3] = pack2(w1.z, w1.w);
            #pragma unroll
            for (int i = 0; i < 8; ++i) {
                const u64 xv = xd[(u + i) & 7];
                #pragma unroll
                for (int j = 0; j < 4; ++j)
                    ffma2(acc2[i][j], xv, wp[j]);
            }
            float v = xs[t0l + h + 8];                    // refill freed ring slot
            xd[u & 7] = pack2(v, v);
        }
    }

    // ---- epilogue: sliding-window stats + affine + bias + relu ----
    float sum = 0.0f, sq = 0.0f;
    #pragma unroll
    for (int h = 0; h < H_; ++h) {
        float v = xs[t0l + h];
        sum += v; sq += v * v;
    }

    float bk[8], sk[8];
    #pragma unroll
    for (int j = 0; j < 8; ++j) { bk[j] = bias[k0 + j]; sk[j] = Sk[k0 + j]; }

    float* __restrict__ outb = out + (size_t)b * LOUT * K_;
    #pragma unroll
    for (int i = 0; i < 8; ++i) {
        if (i) {
            float vo = xs[t0l + i - 1];
            float vn = xs[t0l + i - 1 + H_];
            sum += vn - vo;
            sq  += vn * vn - vo * vo;
        }
        const int t = t_base + t0l + i;
        if (t < LOUT) {
            float mu  = sum * (1.0f / 64.0f);
            float var = (sq - sum * mu) * (1.0f / 63.0f);   // ddof=1
            var = fmaxf(var, 0.0f);
            float inv = 1.0f / (sqrtf(var) + 1e-6f);        // eps added to sd
            float res[8];
            #pragma unroll
            for (int j = 0; j < 4; ++j) {
                float a0, a1; unpack2(acc2[i][j], a0, a1);
                res[2*j]   = fmaxf((a0 - mu * sk[2*j])   * inv + bk[2*j],   0.0f);
                res[2*j+1] = fmaxf((a1 - mu * sk[2*j+1]) * inv + bk[2*j+1], 0.0f);
            }
            float* o = outb + (size_t)t * K_ + k0;
            *(float4*)o       = make_float4(res[0], res[1], res[2], res[3]);
            *(float4*)(o + 4) = make_float4(res[4], res[5], res[6], res[7]);
        }
    }
}

__global__ void fill_tail_kernel(float* p, int n, float v) {
    int i = blockIdx.x * blockDim.x + threadIdx.x;
    if (i < n) p[i] = v;
}

extern "C" void kernel_launch(void* const* d_in, const int* in_sizes, int n_in,
                              void* d_out, int out_size)
{
    const float* x  = (const float*)d_in[0];
    const float* W  = (const float*)d_in[1];
    const float* bb = (const float*)d_in[2];
    float* out = (float*)d_out;

    dim3 grid((LOUT + TILE_T - 1) / TILE_T, B_);
    hankel_fb_kernel<<<grid, TPB>>>(x, W, bb, out);

    long long n_main = (long long)B_ * LOUT * K_;
    if ((long long)out_size > n_main) {
        int extra = (int)((long long)out_size - n_main);
        fill_tail_kernel<<<(extra + 63) / 64, 64>>>(out + n_main, extra, 63.0f);
    }
}

// round 5
// speedup vs baseline: 1.8516x; 1.8516x over previous
#include <cuda_runtime.h>
#include <cuda_bf16.h>

#define B_      16
#define L_      65536
#define H_      64
#define K_      64
#define WARMUP  63
#define LOUT    (L_ - WARMUP)          /* 65473 */
#define TILES_PB 512
#define TOTAL_T  (B_ * TILES_PB)       /* 8192 tiles of 128 rows */
#define GRID     2048
#define CHUNK    (TOTAL_T / GRID)      /* 4 */
#define TPB      128
#define WSTRIDE  72                    /* bf16 row stride for W smem (conflict-free) */

#define MMA_BF16(c, a0, a1, a2, a3, b0, b1)                                   \
    asm volatile("mma.sync.aligned.m16n8k16.row.col.f32.bf16.bf16.f32 "       \
                 "{%0,%1,%2,%3}, {%4,%5,%6,%7}, {%8,%9}, {%0,%1,%2,%3};"      \
                 : "+f"((c)[0]), "+f"((c)[1]), "+f"((c)[2]), "+f"((c)[3])     \
                 : "r"(a0), "r"(a1), "r"(a2), "r"(a3), "r"(b0), "r"(b1))

__device__ __forceinline__ unsigned pack_bf16x2(float v0, float v1) {
    __nv_bfloat16 h0 = __float2bfloat16(v0), h1 = __float2bfloat16(v1);
    return (unsigned)__bfloat16_as_ushort(h0) |
           ((unsigned)__bfloat16_as_ushort(h1) << 16);
}

__global__ __launch_bounds__(TPB)
void hankel_fb_hmma_kernel(const float* __restrict__ x,
                           const float* __restrict__ W,
                           const float* __restrict__ bias,
                           float* __restrict__ out,
                           int extra_tail)
{
    __shared__ float    xs[192];
    __shared__ unsigned xph[192], xpl[192];        /* packed bf16 pairs {x[i],x[i+1]} */
    __shared__ __nv_bfloat16 Wh[K_ * WSTRIDE];     /* hi split, padded rows */
    __shared__ __nv_bfloat16 Wl[K_ * WSTRIDE];     /* lo split */
    __shared__ float invs[128], nmus[128];
    __shared__ float Sks[K_], biass[K_];

    const int tid  = threadIdx.x;
    const int warp = tid >> 5;
    const int lane = tid & 31;
    const int g    = lane >> 2;    /* groupID  (row within 8)   */
    const int q    = lane & 3;     /* thread-in-group (col pair) */

    /* fold harness tail (flattened warmup scalar) into this kernel */
    if (blockIdx.x == 0 && tid == 0 && extra_tail > 0) {
        float* p = out + (long long)B_ * LOUT * K_;
        for (int i = 0; i < extra_tail; ++i) p[i] = 63.0f;
    }

    /* ---- W -> bf16 hi/lo smem (row k, padded to 72) ---- */
    for (int i = tid; i < K_ * H_; i += TPB) {
        int k = i >> 6, h = i & 63;
        float w = W[i];
        __nv_bfloat16 whi = __float2bfloat16(w);
        float rlo = w - __bfloat162float(whi);
        Wh[k * WSTRIDE + h] = whi;
        Wl[k * WSTRIDE + h] = __float2bfloat16(rlo);
    }
    if (tid < K_) {
        float s = 0.0f;
        #pragma unroll
        for (int h = 0; h < H_; ++h) s += W[tid * H_ + h];
        Sks[tid]   = s;
        biass[tid] = bias[tid];
    }
    __syncthreads();

    const unsigned* Whw = (const unsigned*)Wh;   /* word view, row stride 36 */
    const unsigned* Wlw = (const unsigned*)Wl;

    for (int it = 0; it < CHUNK; ++it) {
        const int gidx = blockIdx.x * CHUNK + it;
        const int b    = gidx >> 9;
        const int t0   = (gidx & 511) << 7;

        __syncthreads();  /* previous-iter epilogue done before overwriting smem */

        const float* xb = x + (long long)b * L_;
        for (int i = tid; i < 192; i += TPB) {
            int gi = t0 + i;
            xs[i] = (gi < L_) ? xb[gi] : 0.0f;
        }
        __syncthreads();

        /* packed pair tables: xp[i] = {bf16(x[i]), bf16(x[i+1])} hi/lo */
        for (int i = tid; i < 192; i += TPB) {
            float v0 = xs[i];
            float v1 = (i < 191) ? xs[i + 1] : 0.0f;
            __nv_bfloat16 h0 = __float2bfloat16(v0), h1 = __float2bfloat16(v1);
            float r0 = v0 - __bfloat162float(h0);
            float r1 = v1 - __bfloat162float(h1);
            xph[i] = (unsigned)__bfloat16_as_ushort(h0) |
                     ((unsigned)__bfloat16_as_ushort(h1) << 16);
            xpl[i] = pack_bf16x2(r0, r1);
        }

        /* per-row window stats (row = tid) */
        {
            float sum = 0.0f, sq = 0.0f;
            #pragma unroll
            for (int j = 0; j < H_; ++j) {
                float v = xs[tid + j];
                sum += v; sq += v * v;
            }
            float mu  = sum * (1.0f / 64.0f);
            float var = (sq - sum * mu) * (1.0f / 63.0f);   /* ddof=1 */
            var = fmaxf(var, 0.0f);
            float inv = 1.0f / (sqrtf(var) + 1e-6f);        /* eps on sd */
            invs[tid] = inv;
            nmus[tid] = -mu * inv;
        }
        __syncthreads();

        /* ---- MMA mainloop: warp owns rows 32*warp..+31 (2 m16 tiles), all 64 n ---- */
        float acc[2][8][4];
        #pragma unroll
        for (int mt = 0; mt < 2; ++mt)
            #pragma unroll
            for (int nt = 0; nt < 8; ++nt)
                #pragma unroll
                for (int c = 0; c < 4; ++c) acc[mt][nt][c] = 0.0f;

        const int rbase = warp * 32 + g;

        #pragma unroll
        for (int ks = 0; ks < 4; ++ks) {
            const int k0 = ks * 16;

            /* B fragments: 8 n-tiles x {hi,lo} x 2 regs (conflict-free LDS) */
            unsigned bh[8][2], bl[8][2];
            #pragma unroll
            for (int nt = 0; nt < 8; ++nt) {
                int wi = (nt * 8 + g) * (WSTRIDE / 2) + (k0 >> 1) + q;
                bh[nt][0] = Whw[wi];     bh[nt][1] = Whw[wi + 4];
                bl[nt][0] = Wlw[wi];     bl[nt][1] = Wlw[wi + 4];
            }

            /* A fragments (Hankel: a1 == a2), 3 LDS per split per m-tile */
            unsigned ah[2][3], al[2][3];
            #pragma unroll
            for (int mt = 0; mt < 2; ++mt) {
                int ai = rbase + mt * 16 + k0 + q * 2;
                ah[mt][0] = xph[ai];  ah[mt][1] = xph[ai + 8];  ah[mt][2] = xph[ai + 16];
                al[mt][0] = xpl[ai];  al[mt][1] = xpl[ai + 8];  al[mt][2] = xpl[ai + 16];
            }

            #pragma unroll
            for (int mt = 0; mt < 2; ++mt)
                #pragma unroll
                for (int nt = 0; nt < 8; ++nt) {
                    MMA_BF16(acc[mt][nt], ah[mt][0], ah[mt][1], ah[mt][1], ah[mt][2],
                             bh[nt][0], bh[nt][1]);
                    MMA_BF16(acc[mt][nt], ah[mt][0], ah[mt][1], ah[mt][1], ah[mt][2],
                             bl[nt][0], bl[nt][1]);
                    MMA_BF16(acc[mt][nt], al[mt][0], al[mt][1], al[mt][1], al[mt][2],
                             bh[nt][0], bh[nt][1]);
                }
        }

        /* ---- epilogue: affine normalization + bias + relu + float2 stores ---- */
        float* outb = out + (long long)b * LOUT * K_;
        #pragma unroll
        for (int mt = 0; mt < 2; ++mt) {
            #pragma unroll
            for (int rr = 0; rr < 2; ++rr) {
                const int r = warp * 32 + mt * 16 + rr * 8 + g;
                const int t = t0 + r;
                if (t < LOUT) {
                    const float inv = invs[r];
                    const float nm  = nmus[r];
                    float* o = outb + (long long)t * K_ + q * 2;
                    #pragma unroll
                    for (int nt = 0; nt < 8; ++nt) {
                        const int n = nt * 8 + q * 2;
                        float2 sk = *(const float2*)&Sks[n];
                        float2 bi = *(const float2*)&biass[n];
                        float2 res;
                        res.x = fmaxf(fmaf(acc[mt][nt][rr * 2 + 0], inv, fmaf(nm, sk.x, bi.x)), 0.0f);
                        res.y = fmaxf(fmaf(acc[mt][nt][rr * 2 + 1], inv, fmaf(nm, sk.y, bi.y)), 0.0f);
                        *(float2*)(o + nt * 8) = res;
                    }
                }
            }
        }
    }
}

extern "C" void kernel_launch(void* const* d_in, const int* in_sizes, int n_in,
                              void* d_out, int out_size)
{
    const float* x  = (const float*)d_in[0];
    const float* W  = (const float*)d_in[1];
    const float* bb = (const float*)d_in[2];
    float* out = (float*)d_out;

    long long n_main = (long long)B_ * LOUT * K_;
    int extra = (int)((long long)out_size - n_main);
    if (extra < 0) extra = 0;

    hankel_fb_hmma_kernel<<<GRID, TPB>>>(x, W, bb, out, extra);
}